// round 16
// baseline (speedup 1.0000x reference)
#include <cuda_runtime.h>
#include <cuda_fp16.h>
#include <math.h>
#include <stdint.h>

#define BB 2
#define SS 2048
#define HH 1024
#define NHH 16
#define HD 64
#define BS (BB*SS)     /* 4096 rows */
#define H3 (3*HH)      /* 3072 */

// ---------------- scratch (no allocations allowed) ----------------
__device__ __half g_xn [BS*HH];   // 8 MiB (fp16)
__device__ __half g_qkv[BS*H3];   // 24 MiB (fp16)
__device__ __half g_ctx[BS*HH];   // 8 MiB (fp16)
__device__ __half g_wq [HH*H3];   // 6 MiB (fp16, transposed [N][K])
__device__ __half g_wo [HH*HH];   // 2 MiB (fp16, transposed [N][K])

// ---------------- helpers ----------------
__device__ __forceinline__ void mma_f16(float* c, const uint32_t* a, const uint32_t* b) {
    asm volatile("mma.sync.aligned.m16n8k16.row.col.f32.f16.f16.f32 "
        "{%0,%1,%2,%3}, {%4,%5,%6,%7}, {%8,%9}, {%0,%1,%2,%3};"
        : "+f"(c[0]), "+f"(c[1]), "+f"(c[2]), "+f"(c[3])
        : "r"(a[0]), "r"(a[1]), "r"(a[2]), "r"(a[3]), "r"(b[0]), "r"(b[1]));
}
__device__ __forceinline__ void cp16(uint32_t s, const void* g) {
    asm volatile("cp.async.cg.shared.global [%0], [%1], 16;" :: "r"(s), "l"(g));
}
#define CP_COMMIT asm volatile("cp.async.commit_group;")
__device__ __forceinline__ uint32_t s2u(const void* p) {
    return (uint32_t)__cvta_generic_to_shared(p);
}
__device__ __forceinline__ uint32_t packh2(float a, float b) {
    __half2 h = __floats2half2_rn(a, b);
    return *(uint32_t*)&h;
}

// ---------------- weight transpose + fp16: in[K][N] fp32 -> out[N][K] fp16 ----------------
__global__ __launch_bounds__(256) void transpose_w(const float* __restrict__ in,
                                                   __half* __restrict__ out,
                                                   int Kd, int Nd)
{
    __shared__ float t[32][33];
    int n0 = blockIdx.x << 5, k0 = blockIdx.y << 5;
    int x = threadIdx.x, y = threadIdx.y;
#pragma unroll
    for (int i = 0; i < 32; i += 8)
        t[y + i][x] = in[(size_t)(k0 + y + i) * Nd + n0 + x];
    __syncthreads();
#pragma unroll
    for (int i = 0; i < 32; i += 8)
        out[(size_t)(n0 + y + i) * Kd + k0 + x] = __float2half_rn(t[x][y + i]);
}

// ---------------- LayerNorm (fp16 output) ----------------
__global__ __launch_bounds__(256) void ln_kernel(const float* __restrict__ x,
                                                 const float* __restrict__ w,
                                                 const float* __restrict__ bb,
                                                 __half* __restrict__ out)
{
    int row = blockIdx.x;
    int t = threadIdx.x;
    const float* xr = x + (size_t)row*HH;
    float v[4];
    float s = 0.f, sq = 0.f;
#pragma unroll
    for (int i = 0; i < 4; i++) { v[i] = xr[t + 256*i]; s += v[i]; sq += v[i]*v[i]; }
#pragma unroll
    for (int o = 16; o; o >>= 1) {
        s  += __shfl_xor_sync(0xffffffffu, s,  o);
        sq += __shfl_xor_sync(0xffffffffu, sq, o);
    }
    __shared__ float rs[8], rq[8];
    if ((t & 31) == 0) { rs[t>>5] = s; rq[t>>5] = sq; }
    __syncthreads();
    if (t < 32) {
        s  = (t < 8) ? rs[t] : 0.f;
        sq = (t < 8) ? rq[t] : 0.f;
#pragma unroll
        for (int o = 4; o; o >>= 1) {
            s  += __shfl_xor_sync(0xffffffffu, s,  o);
            sq += __shfl_xor_sync(0xffffffffu, sq, o);
        }
        if (t == 0) { rs[0] = s; rq[0] = sq; }
    }
    __syncthreads();
    float mu  = rs[0] * (1.0f/HH);
    float var = rq[0] * (1.0f/HH) - mu*mu;
    float inv = rsqrtf(var + 1e-5f);
    __half* orow = out + (size_t)row*HH;
#pragma unroll
    for (int i = 0; i < 4; i++) {
        int c = t + 256*i;
        orow[c] = __float2half_rn((v[i] - mu) * inv * w[c] + bb[c]);
    }
}

// ---------------- FP16 GEMM core: 128x128x32, 4 warps x (64x64), 4-stage cp.async ----------
#define GEMM_STAGES 4
#define GEMM_SMEM (GEMM_STAGES * 2 * 128 * 20 * 4)   /* 81920 B */

template <typename OutT>
__device__ __forceinline__ void gemm_body(const __half* A, const __half* Bt,
                                          const float* bias, OutT* C,
                                          int M, int N, int K, uint32_t* dsm)
{
    uint32_t (*As)[128][20] = (uint32_t (*)[128][20])dsm;
    uint32_t (*Bs)[128][20] = (uint32_t (*)[128][20])(dsm + GEMM_STAGES*128*20);

    int tid  = threadIdx.x;
    int lane = tid & 31, warp = tid >> 5;
    int bm = blockIdx.y << 7, bn = blockIdx.x << 7;
    int warpM = (warp >> 1) << 6;
    int warpN = (warp & 1) << 6;

    const __half* aRow = A  + (size_t)(bm + tid) * K;
    const __half* bRow = Bt + (size_t)(bn + tid) * K;

    uint32_t sA = s2u(&As[0][tid][0]);
    uint32_t sB = s2u(&Bs[0][tid][0]);
    const uint32_t STG = 128u * 20u * 4u;

    const int nch = K >> 5;

#pragma unroll
    for (int s = 0; s < GEMM_STAGES - 1; s++) {
        uint32_t ofs = (uint32_t)s * STG;
        const __half* ap = aRow + s * 32;
        const __half* bp = bRow + s * 32;
#pragma unroll
        for (int u = 0; u < 4; u++) {
            cp16(sA + ofs + u*16, ap + u*8);
            cp16(sB + ofs + u*16, bp + u*8);
        }
        CP_COMMIT;
    }

    float acc[4][8][4];
#pragma unroll
    for (int mt = 0; mt < 4; mt++)
#pragma unroll
        for (int nt = 0; nt < 8; nt++)
#pragma unroll
            for (int e = 0; e < 4; e++) acc[mt][nt][e] = 0.f;

    int am  = warpM + (lane >> 2);
    int bn0 = warpN + (lane >> 2);
    int kq  = lane & 3;

    for (int c = 0; c < nch; c++) {
        asm volatile("cp.async.wait_group 2;" ::: "memory");
        __syncthreads();
        int st = c & (GEMM_STAGES - 1);

        if (c + GEMM_STAGES - 1 < nch) {
            uint32_t nofs = (uint32_t)((c + GEMM_STAGES - 1) & (GEMM_STAGES - 1)) * STG;
            const __half* ap = aRow + (c + GEMM_STAGES - 1) * 32;
            const __half* bp = bRow + (c + GEMM_STAGES - 1) * 32;
#pragma unroll
            for (int u = 0; u < 4; u++) {
                cp16(sA + nofs + u*16, ap + u*8);
                cp16(sB + nofs + u*16, bp + u*8);
            }
        }
        CP_COMMIT;

#pragma unroll
        for (int ks = 0; ks < 2; ks++) {
            int base = ks * 8;
            uint32_t af[4][4], bf[8][2];
#pragma unroll
            for (int mt = 0; mt < 4; mt++) {
                int m = am + mt*16;
                af[mt][0] = As[st][m    ][base + kq];
                af[mt][1] = As[st][m + 8][base + kq];
                af[mt][2] = As[st][m    ][base + kq + 4];
                af[mt][3] = As[st][m + 8][base + kq + 4];
            }
#pragma unroll
            for (int nt = 0; nt < 8; nt++) {
                int n = bn0 + nt*8;
                bf[nt][0] = Bs[st][n][base + kq];
                bf[nt][1] = Bs[st][n][base + kq + 4];
            }
#pragma unroll
            for (int mt = 0; mt < 4; mt++)
#pragma unroll
                for (int nt = 0; nt < 8; nt++)
                    mma_f16(acc[mt][nt], af[mt], bf[nt]);
        }
    }

#pragma unroll
    for (int mt = 0; mt < 4; mt++) {
        int row0 = bm + warpM + mt*16 + (lane >> 2);
#pragma unroll
        for (int nt = 0; nt < 8; nt++) {
            int col = bn + warpN + nt*8 + ((lane & 3) << 1);
            float b0 = bias[col], b1 = bias[col + 1];
            float r00 = acc[mt][nt][0] + b0, r01 = acc[mt][nt][1] + b1;
            float r10 = acc[mt][nt][2] + b0, r11 = acc[mt][nt][3] + b1;
            if (sizeof(OutT) == 2) {
                __half2 h0 = __floats2half2_rn(r00, r01);
                __half2 h1 = __floats2half2_rn(r10, r11);
                *(__half2*)((__half*)C + (size_t)row0 * N + col)       = h0;
                *(__half2*)((__half*)C + (size_t)(row0 + 8) * N + col) = h1;
            } else {
                *(float2*)((float*)C + (size_t)row0 * N + col)       = make_float2(r00, r01);
                *(float2*)((float*)C + (size_t)(row0 + 8) * N + col) = make_float2(r10, r11);
            }
        }
    }
}

__global__ __launch_bounds__(128, 2) void fp16_gemm_h(const __half* __restrict__ A,
                                                      const __half* __restrict__ Bt,
                                                      const float* __restrict__ bias,
                                                      __half* __restrict__ C,
                                                      int M, int N, int K)
{
    extern __shared__ uint32_t dsm[];
    gemm_body<__half>(A, Bt, bias, C, M, N, K, dsm);
}
__global__ __launch_bounds__(128, 2) void fp16_gemm_f(const __half* __restrict__ A,
                                                      const __half* __restrict__ Bt,
                                                      const float* __restrict__ bias,
                                                      float* __restrict__ C,
                                                      int M, int N, int K)
{
    extern __shared__ uint32_t dsm[];
    gemm_body<float>(A, Bt, bias, C, M, N, K, dsm);
}

// ---------------- Rotary (fp16 in/out) ----------------
__global__ __launch_bounds__(256) void rotary_kernel(__half* __restrict__ qkv)
{
    int idx = blockIdx.x * blockDim.x + threadIdx.x;
    int d   = idx & 31;
    int h   = (idx >> 5) & (NHH - 1);
    int row = idx >> 9;
    int pos = row & (SS - 1);

    const float k = 0.28782313662425575f;   // ln(10000)/32
    float invf = expf(-k * (float)d);
    float fr = (float)pos * invf;
    float c = cosf(fr), sn = sinf(fr);

    __half* qp = qkv + (size_t)row * H3 + h * HD;
    __half* kp = qp + HH;

    float x1 = __half2float(qp[d]), x2 = __half2float(qp[d + 32]);
    qp[d]      = __float2half_rn(x1 * c - x2 * sn);
    qp[d + 32] = __float2half_rn(x2 * c + x1 * sn);

    x1 = __half2float(kp[d]); x2 = __half2float(kp[d + 32]);
    kp[d]      = __float2half_rn(x1 * c - x2 * sn);
    kp[d + 32] = __float2half_rn(x2 * c + x1 * sn);
}

// ---------------- Flash attention, FP16, 32-key tiles, longest-first scheduling -----------
// 64 q rows x 1 head per block, 4 warps (16 q rows each), 32-key tiles.
// blockIdx.x is REVERSED onto qb so the heaviest (largest-qb, causal) blocks
// are scheduled first and the tail wave runs the 2-tile blocks.
__global__ __launch_bounds__(128, 3) void attn_tc_kernel(const __half* __restrict__ qkv,
                                                         const int* __restrict__ mask,
                                                         __half* __restrict__ ctx)
{
    __shared__ __align__(16) __half Ksh[2][32][72];  // [key][dim]
    __shared__ __align__(16) __half Vth[2][64][42];  // [dim][key]
    __shared__ float Bias[2][32];

    int qb = (gridDim.x - 1) - blockIdx.x;           // longest-first
    int h = blockIdx.y, b = blockIdx.z;
    int tid = threadIdx.x, w = tid >> 5, lane = tid & 31;
    int gq = lane >> 2, tq = lane & 3;

    // Q fragments (fp16, pre-scaled)
    const __half* qbase = qkv + ((size_t)(b*SS) + qb*64 + w*16) * H3 + h*HD;
    uint32_t qf[4][4];
#pragma unroll
    for (int j = 0; j < 4; j++) {
        const __half* q0 = qbase + (size_t)gq*H3     + j*16 + 2*tq;
        const __half* q1 = qbase + (size_t)(gq+8)*H3 + j*16 + 2*tq;
        __half2 a0 = *(const __half2*)(q0);
        __half2 a1 = *(const __half2*)(q1);
        __half2 a2 = *(const __half2*)(q0 + 8);
        __half2 a3 = *(const __half2*)(q1 + 8);
        qf[j][0] = packh2(__low2float(a0)*0.125f, __high2float(a0)*0.125f);
        qf[j][1] = packh2(__low2float(a1)*0.125f, __high2float(a1)*0.125f);
        qf[j][2] = packh2(__low2float(a2)*0.125f, __high2float(a2)*0.125f);
        qf[j][3] = packh2(__low2float(a3)*0.125f, __high2float(a3)*0.125f);
    }

    float o[8][4];
#pragma unroll
    for (int nt = 0; nt < 8; nt++)
#pragma unroll
        for (int e = 0; e < 4; e++) o[nt][e] = 0.f;
    float m0 = -1e30f, m1 = -1e30f, l0 = 0.f, l1 = 0.f;

    int row0 = qb*64 + w*16 + gq;
    int ntiles = 2*qb + 2;

    // loader coords: thread handles key rows lr+8*it (it=0..3), dims lc..lc+3
    int lr = tid >> 4, lc = (tid & 15) << 2;

    uint2  kreg[4], vreg[4];
    float  breg = 0.f;

    const __half* kbase0 = qkv + (size_t)(b*SS) * H3 + HH + h*HD;

    // ---- prologue: load tile 0 ----
    {
        const __half* kb = kbase0;
        const __half* vb = kb + HH;
#pragma unroll
        for (int it = 0; it < 4; it++) {
            int r = lr + it*8;
            kreg[it] = *(const uint2*)(kb + (size_t)r*H3 + lc);
            vreg[it] = *(const uint2*)(vb + (size_t)r*H3 + lc);
        }
        if (tid < 32) breg = (1.0f - (float)mask[b*SS + tid]) * -10000.0f;
#pragma unroll
        for (int it = 0; it < 4; it++) {
            int r = lr + it*8;
            *(uint2*)&Ksh[0][r][lc] = kreg[it];          // raw fp16 copy
            __half2 v0 = *(__half2*)&vreg[it].x;
            __half2 v1 = *(__half2*)&vreg[it].y;
            Vth[0][lc+0][r] = __low2half(v0);
            Vth[0][lc+1][r] = __high2half(v0);
            Vth[0][lc+2][r] = __low2half(v1);
            Vth[0][lc+3][r] = __high2half(v1);
        }
        if (tid < 32) Bias[0][tid] = breg;
    }
    __syncthreads();

    for (int kt = 0; kt < ntiles; kt++) {
        int buf = kt & 1;
        bool more = (kt + 1) < ntiles;

        // issue next tile's global loads (hidden behind compute)
        if (more) {
            const __half* kb = kbase0 + (size_t)((kt+1)*32) * H3;
            const __half* vb = kb + HH;
#pragma unroll
            for (int it = 0; it < 4; it++) {
                int r = lr + it*8;
                kreg[it] = *(const uint2*)(kb + (size_t)r*H3 + lc);
                vreg[it] = *(const uint2*)(vb + (size_t)r*H3 + lc);
            }
            if (tid < 32) breg = (1.0f - (float)mask[b*SS + (kt+1)*32 + tid]) * -10000.0f;
        }

        // ---- S = Q K^T (fp16, 16 MMAs) ----
        float sc[4][4];
#pragma unroll
        for (int nt = 0; nt < 4; nt++)
#pragma unroll
            for (int e = 0; e < 4; e++) sc[nt][e] = 0.f;

#pragma unroll
        for (int j = 0; j < 4; j++) {
#pragma unroll
            for (int nt = 0; nt < 4; nt++) {
                uint32_t bh[2];
                bh[0] = *(const uint32_t*)&Ksh[buf][nt*8 + gq][j*16 + 2*tq];
                bh[1] = *(const uint32_t*)&Ksh[buf][nt*8 + gq][j*16 + 8 + 2*tq];
                mma_f16(sc[nt], qf[j], bh);
            }
        }

        // ---- bias + causal mask ----
#pragma unroll
        for (int nt = 0; nt < 4; nt++) {
            int k0 = kt*32 + nt*8 + 2*tq;
            float bs0 = Bias[buf][nt*8 + 2*tq], bs1 = Bias[buf][nt*8 + 2*tq + 1];
            sc[nt][0] += bs0; sc[nt][1] += bs1;
            sc[nt][2] += bs0; sc[nt][3] += bs1;
            if (k0     > row0)     sc[nt][0] = -10000.0f;
            if (k0 + 1 > row0)     sc[nt][1] = -10000.0f;
            if (k0     > row0 + 8) sc[nt][2] = -10000.0f;
            if (k0 + 1 > row0 + 8) sc[nt][3] = -10000.0f;
        }

        // ---- online softmax (deferred l-reduction) ----
        float tm0 = -1e30f, tm1 = -1e30f;
#pragma unroll
        for (int nt = 0; nt < 4; nt++) {
            tm0 = fmaxf(tm0, fmaxf(sc[nt][0], sc[nt][1]));
            tm1 = fmaxf(tm1, fmaxf(sc[nt][2], sc[nt][3]));
        }
        tm0 = fmaxf(tm0, __shfl_xor_sync(0xffffffffu, tm0, 1));
        tm0 = fmaxf(tm0, __shfl_xor_sync(0xffffffffu, tm0, 2));
        tm1 = fmaxf(tm1, __shfl_xor_sync(0xffffffffu, tm1, 1));
        tm1 = fmaxf(tm1, __shfl_xor_sync(0xffffffffu, tm1, 2));

        float nm0 = fmaxf(m0, tm0), nm1 = fmaxf(m1, tm1);
        float c0 = __expf(m0 - nm0), c1 = __expf(m1 - nm1);
        m0 = nm0; m1 = nm1;

        float s0 = 0.f, s1 = 0.f;
#pragma unroll
        for (int nt = 0; nt < 4; nt++) {
            sc[nt][0] = __expf(sc[nt][0] - nm0); s0 += sc[nt][0];
            sc[nt][1] = __expf(sc[nt][1] - nm0); s0 += sc[nt][1];
            sc[nt][2] = __expf(sc[nt][2] - nm1); s1 += sc[nt][2];
            sc[nt][3] = __expf(sc[nt][3] - nm1); s1 += sc[nt][3];
        }
        l0 = l0*c0 + s0;
        l1 = l1*c1 + s1;

#pragma unroll
        for (int nt = 0; nt < 8; nt++) {
            o[nt][0] *= c0; o[nt][1] *= c0;
            o[nt][2] *= c1; o[nt][3] *= c1;
        }

        // ---- O += P V (shuffle-free fp16 PV, 16 MMAs) ----
#pragma unroll
        for (int c = 0; c < 2; c++) {
            uint32_t a[4];
            a[0] = packh2(sc[2*c    ][0], sc[2*c    ][1]);
            a[1] = packh2(sc[2*c    ][2], sc[2*c    ][3]);
            a[2] = packh2(sc[2*c + 1][0], sc[2*c + 1][1]);
            a[3] = packh2(sc[2*c + 1][2], sc[2*c + 1][3]);
#pragma unroll
            for (int nt = 0; nt < 8; nt++) {
                uint32_t bv[2];
                bv[0] = *(const uint32_t*)&Vth[buf][nt*8 + gq][c*16 + 2*tq];
                bv[1] = *(const uint32_t*)&Vth[buf][nt*8 + gq][c*16 + 8 + 2*tq];
                mma_f16(o[nt], a, bv);
            }
        }

        // ---- store next tile into the other buffer ----
        if (more) {
            int nb = buf ^ 1;
#pragma unroll
            for (int it = 0; it < 4; it++) {
                int r = lr + it*8;
                *(uint2*)&Ksh[nb][r][lc] = kreg[it];
                __half2 v0 = *(__half2*)&vreg[it].x;
                __half2 v1 = *(__half2*)&vreg[it].y;
                Vth[nb][lc+0][r] = __low2half(v0);
                Vth[nb][lc+1][r] = __high2half(v0);
                Vth[nb][lc+2][r] = __low2half(v1);
                Vth[nb][lc+3][r] = __high2half(v1);
            }
            if (tid < 32) Bias[nb][tid] = breg;
        }
        __syncthreads();
    }

    // ---- epilogue ----
    l0 += __shfl_xor_sync(0xffffffffu, l0, 1);
    l0 += __shfl_xor_sync(0xffffffffu, l0, 2);
    l1 += __shfl_xor_sync(0xffffffffu, l1, 1);
    l1 += __shfl_xor_sync(0xffffffffu, l1, 2);
    float inv0 = 1.0f / l0, inv1 = 1.0f / l1;
    __half* cb = ctx + ((size_t)(b*SS) + qb*64 + w*16) * HH + h*HD;
#pragma unroll
    for (int nt = 0; nt < 8; nt++) {
        __half2 u0 = __floats2half2_rn(o[nt][0]*inv0, o[nt][1]*inv0);
        __half2 u1 = __floats2half2_rn(o[nt][2]*inv1, o[nt][3]*inv1);
        *(__half2*)(cb + (size_t)gq*HH      + nt*8 + 2*tq) = u0;
        *(__half2*)(cb + (size_t)(gq+8)*HH  + nt*8 + 2*tq) = u1;
    }
}

// ---------------- launch ----------------
extern "C" void kernel_launch(void* const* d_in, const int* in_sizes, int n_in,
                              void* d_out, int out_size)
{
    const float* x     = (const float*)d_in[0];
    const int*   maskp = (const int*)  d_in[1];
    const float* nw    = (const float*)d_in[2];
    const float* nb    = (const float*)d_in[3];
    const float* qkvw  = (const float*)d_in[4];
    const float* qkvb  = (const float*)d_in[5];
    const float* ow    = (const float*)d_in[6];
    const float* ob    = (const float*)d_in[7];
    float* out = (float*)d_out;

    __half *xn, *qkvB, *ctx, *wq, *wo;
    cudaGetSymbolAddress((void**)&xn,   g_xn);
    cudaGetSymbolAddress((void**)&qkvB, g_qkv);
    cudaGetSymbolAddress((void**)&ctx,  g_ctx);
    cudaGetSymbolAddress((void**)&wq,   g_wq);
    cudaGetSymbolAddress((void**)&wo,   g_wo);

    cudaFuncSetAttribute(fp16_gemm_h, cudaFuncAttributeMaxDynamicSharedMemorySize, GEMM_SMEM);
    cudaFuncSetAttribute(fp16_gemm_f, cudaFuncAttributeMaxDynamicSharedMemorySize, GEMM_SMEM);

    ln_kernel<<<BS, 256>>>(x, nw, nb, xn);
    transpose_w<<<dim3(H3/32, HH/32), dim3(32, 8)>>>(qkvw, wq, HH, H3);
    transpose_w<<<dim3(HH/32, HH/32), dim3(32, 8)>>>(ow,   wo, HH, HH);
    fp16_gemm_h<<<dim3(H3/128, BS/128), 128, GEMM_SMEM>>>(xn, wq, qkvb, qkvB, BS, H3, HH);
    rotary_kernel<<<(BS*NHH*32)/256, 256>>>(qkvB);
    attn_tc_kernel<<<dim3(SS/64, NHH, BB), 128>>>(qkvB, maskp, ctx);
    fp16_gemm_f<<<dim3(HH/128, BS/128), 128, GEMM_SMEM>>>(ctx, wo, ob, out, BS, HH, HH);
}

// round 17
// speedup vs baseline: 1.0286x; 1.0286x over previous
#include <cuda_runtime.h>
#include <cuda_fp16.h>
#include <math.h>
#include <stdint.h>

#define BB 2
#define SS 2048
#define HH 1024
#define NHH 16
#define HD 64
#define BS (BB*SS)     /* 4096 rows */
#define H3 (3*HH)      /* 3072 */

// ---------------- scratch (no allocations allowed) ----------------
__device__ __half g_xn [BS*HH];   // 8 MiB (fp16)
__device__ __half g_qkv[BS*H3];   // 24 MiB (fp16)
__device__ __half g_ctx[BS*HH];   // 8 MiB (fp16)
__device__ __half g_wq [HH*H3];   // 6 MiB (fp16, transposed [N][K])
__device__ __half g_wo [HH*HH];   // 2 MiB (fp16, transposed [N][K])

// ---------------- helpers ----------------
__device__ __forceinline__ void mma_f16(float* c, const uint32_t* a, const uint32_t* b) {
    asm volatile("mma.sync.aligned.m16n8k16.row.col.f32.f16.f16.f32 "
        "{%0,%1,%2,%3}, {%4,%5,%6,%7}, {%8,%9}, {%0,%1,%2,%3};"
        : "+f"(c[0]), "+f"(c[1]), "+f"(c[2]), "+f"(c[3])
        : "r"(a[0]), "r"(a[1]), "r"(a[2]), "r"(a[3]), "r"(b[0]), "r"(b[1]));
}
__device__ __forceinline__ void cp16(uint32_t s, const void* g) {
    asm volatile("cp.async.cg.shared.global [%0], [%1], 16;" :: "r"(s), "l"(g));
}
#define CP_COMMIT asm volatile("cp.async.commit_group;")
__device__ __forceinline__ uint32_t s2u(const void* p) {
    return (uint32_t)__cvta_generic_to_shared(p);
}
__device__ __forceinline__ uint32_t packh2(float a, float b) {
    __half2 h = __floats2half2_rn(a, b);
    return *(uint32_t*)&h;
}

// ---------------- weight transpose + fp16: in[K][N] fp32 -> out[N][K] fp16 ----------------
__global__ __launch_bounds__(256) void transpose_w(const float* __restrict__ in,
                                                   __half* __restrict__ out,
                                                   int Kd, int Nd)
{
    __shared__ float t[32][33];
    int n0 = blockIdx.x << 5, k0 = blockIdx.y << 5;
    int x = threadIdx.x, y = threadIdx.y;
#pragma unroll
    for (int i = 0; i < 32; i += 8)
        t[y + i][x] = in[(size_t)(k0 + y + i) * Nd + n0 + x];
    __syncthreads();
#pragma unroll
    for (int i = 0; i < 32; i += 8)
        out[(size_t)(n0 + y + i) * Kd + k0 + x] = __float2half_rn(t[x][y + i]);
}

// ---------------- LayerNorm (fp16 output) ----------------
__global__ __launch_bounds__(256) void ln_kernel(const float* __restrict__ x,
                                                 const float* __restrict__ w,
                                                 const float* __restrict__ bb,
                                                 __half* __restrict__ out)
{
    int row = blockIdx.x;
    int t = threadIdx.x;
    const float* xr = x + (size_t)row*HH;
    float v[4];
    float s = 0.f, sq = 0.f;
#pragma unroll
    for (int i = 0; i < 4; i++) { v[i] = xr[t + 256*i]; s += v[i]; sq += v[i]*v[i]; }
#pragma unroll
    for (int o = 16; o; o >>= 1) {
        s  += __shfl_xor_sync(0xffffffffu, s,  o);
        sq += __shfl_xor_sync(0xffffffffu, sq, o);
    }
    __shared__ float rs[8], rq[8];
    if ((t & 31) == 0) { rs[t>>5] = s; rq[t>>5] = sq; }
    __syncthreads();
    if (t < 32) {
        s  = (t < 8) ? rs[t] : 0.f;
        sq = (t < 8) ? rq[t] : 0.f;
#pragma unroll
        for (int o = 4; o; o >>= 1) {
            s  += __shfl_xor_sync(0xffffffffu, s,  o);
            sq += __shfl_xor_sync(0xffffffffu, sq, o);
        }
        if (t == 0) { rs[0] = s; rq[0] = sq; }
    }
    __syncthreads();
    float mu  = rs[0] * (1.0f/HH);
    float var = rq[0] * (1.0f/HH) - mu*mu;
    float inv = rsqrtf(var + 1e-5f);
    __half* orow = out + (size_t)row*HH;
#pragma unroll
    for (int i = 0; i < 4; i++) {
        int c = t + 256*i;
        orow[c] = __float2half_rn((v[i] - mu) * inv * w[c] + bb[c]);
    }
}

// ---------------- FP16 GEMM core: 128x128x32, 4 warps x (64x64), 4-stage cp.async ----------
// ROT: apply rotary in the epilogue to columns < 2*HH (Q and K regions).
// Head dim 64 == warp-N tile width; rotary pair (d, d+32) == acc pair (nt, nt+4).
#define GEMM_STAGES 4
#define GEMM_SMEM (GEMM_STAGES * 2 * 128 * 20 * 4)   /* 81920 B */
#define ROT_K 0.28782313662425575f                    /* ln(10000)/32 */

template <typename OutT, bool ROT>
__device__ __forceinline__ void gemm_body(const __half* A, const __half* Bt,
                                          const float* bias, OutT* C,
                                          int M, int N, int K, uint32_t* dsm)
{
    uint32_t (*As)[128][20] = (uint32_t (*)[128][20])dsm;
    uint32_t (*Bs)[128][20] = (uint32_t (*)[128][20])(dsm + GEMM_STAGES*128*20);

    int tid  = threadIdx.x;
    int lane = tid & 31, warp = tid >> 5;
    int bm = blockIdx.y << 7, bn = blockIdx.x << 7;
    int warpM = (warp >> 1) << 6;
    int warpN = (warp & 1) << 6;

    const __half* aRow = A  + (size_t)(bm + tid) * K;
    const __half* bRow = Bt + (size_t)(bn + tid) * K;

    uint32_t sA = s2u(&As[0][tid][0]);
    uint32_t sB = s2u(&Bs[0][tid][0]);
    const uint32_t STG = 128u * 20u * 4u;

    const int nch = K >> 5;

#pragma unroll
    for (int s = 0; s < GEMM_STAGES - 1; s++) {
        uint32_t ofs = (uint32_t)s * STG;
        const __half* ap = aRow + s * 32;
        const __half* bp = bRow + s * 32;
#pragma unroll
        for (int u = 0; u < 4; u++) {
            cp16(sA + ofs + u*16, ap + u*8);
            cp16(sB + ofs + u*16, bp + u*8);
        }
        CP_COMMIT;
    }

    float acc[4][8][4];
#pragma unroll
    for (int mt = 0; mt < 4; mt++)
#pragma unroll
        for (int nt = 0; nt < 8; nt++)
#pragma unroll
            for (int e = 0; e < 4; e++) acc[mt][nt][e] = 0.f;

    int am  = warpM + (lane >> 2);
    int bn0 = warpN + (lane >> 2);
    int kq  = lane & 3;

    for (int c = 0; c < nch; c++) {
        asm volatile("cp.async.wait_group 2;" ::: "memory");
        __syncthreads();
        int st = c & (GEMM_STAGES - 1);

        if (c + GEMM_STAGES - 1 < nch) {
            uint32_t nofs = (uint32_t)((c + GEMM_STAGES - 1) & (GEMM_STAGES - 1)) * STG;
            const __half* ap = aRow + (c + GEMM_STAGES - 1) * 32;
            const __half* bp = bRow + (c + GEMM_STAGES - 1) * 32;
#pragma unroll
            for (int u = 0; u < 4; u++) {
                cp16(sA + nofs + u*16, ap + u*8);
                cp16(sB + nofs + u*16, bp + u*8);
            }
        }
        CP_COMMIT;

#pragma unroll
        for (int ks = 0; ks < 2; ks++) {
            int base = ks * 8;
            uint32_t af[4][4], bf[8][2];
#pragma unroll
            for (int mt = 0; mt < 4; mt++) {
                int m = am + mt*16;
                af[mt][0] = As[st][m    ][base + kq];
                af[mt][1] = As[st][m + 8][base + kq];
                af[mt][2] = As[st][m    ][base + kq + 4];
                af[mt][3] = As[st][m + 8][base + kq + 4];
            }
#pragma unroll
            for (int nt = 0; nt < 8; nt++) {
                int n = bn0 + nt*8;
                bf[nt][0] = Bs[st][n][base + kq];
                bf[nt][1] = Bs[st][n][base + kq + 4];
            }
#pragma unroll
            for (int mt = 0; mt < 4; mt++)
#pragma unroll
                for (int nt = 0; nt < 8; nt++)
                    mma_f16(acc[mt][nt], af[mt], bf[nt]);
        }
    }

    // ---- epilogue: bias (+ optional rotary on register pairs), store ----
    bool rot = ROT && (bn + warpN) < 2*HH;   // Q/K columns only

    // inv_freq for this thread's two d values (depends on nt, tq only)
    float invf0[4], invf1[4];
    if (rot) {
#pragma unroll
        for (int nt = 0; nt < 4; nt++) {
            int d0 = nt*8 + ((lane & 3) << 1);
            invf0[nt] = expf(-ROT_K * (float)d0);
            invf1[nt] = expf(-ROT_K * (float)(d0 + 1));
        }
    }

#pragma unroll
    for (int mt = 0; mt < 4; mt++) {
        int row0 = bm + warpM + mt*16 + (lane >> 2);
        float pos0 = (float)(row0 & (SS - 1));
        float pos8 = (float)((row0 + 8) & (SS - 1));
#pragma unroll
        for (int nt = 0; nt < 4; nt++) {
            int col = bn + warpN + nt*8 + ((lane & 3) << 1);
            float b0  = bias[col],      b1  = bias[col + 1];
            float b0p = bias[col + 32], b1p = bias[col + 33];
            // x: low half (d), y: high half (d+32)
            float x00 = acc[mt][nt  ][0] + b0,  x01 = acc[mt][nt  ][1] + b1;
            float x10 = acc[mt][nt  ][2] + b0,  x11 = acc[mt][nt  ][3] + b1;
            float y00 = acc[mt][nt+4][0] + b0p, y01 = acc[mt][nt+4][1] + b1p;
            float y10 = acc[mt][nt+4][2] + b0p, y11 = acc[mt][nt+4][3] + b1p;

            if (rot) {
                float c00, s00, c01, s01, c80, s80, c81, s81;
                __sincosf(pos0 * invf0[nt], &s00, &c00);
                __sincosf(pos0 * invf1[nt], &s01, &c01);
                __sincosf(pos8 * invf0[nt], &s80, &c80);
                __sincosf(pos8 * invf1[nt], &s81, &c81);
                float nx00 = x00*c00 - y00*s00, ny00 = y00*c00 + x00*s00;
                float nx01 = x01*c01 - y01*s01, ny01 = y01*c01 + x01*s01;
                float nx10 = x10*c80 - y10*s80, ny10 = y10*c80 + x10*s80;
                float nx11 = x11*c81 - y11*s81, ny11 = y11*c81 + x11*s81;
                x00 = nx00; x01 = nx01; x10 = nx10; x11 = nx11;
                y00 = ny00; y01 = ny01; y10 = ny10; y11 = ny11;
            }

            if (sizeof(OutT) == 2) {
                *(__half2*)((__half*)C + (size_t)row0 * N + col)            = __floats2half2_rn(x00, x01);
                *(__half2*)((__half*)C + (size_t)(row0 + 8) * N + col)      = __floats2half2_rn(x10, x11);
                *(__half2*)((__half*)C + (size_t)row0 * N + col + 32)       = __floats2half2_rn(y00, y01);
                *(__half2*)((__half*)C + (size_t)(row0 + 8) * N + col + 32) = __floats2half2_rn(y10, y11);
            } else {
                *(float2*)((float*)C + (size_t)row0 * N + col)            = make_float2(x00, x01);
                *(float2*)((float*)C + (size_t)(row0 + 8) * N + col)      = make_float2(x10, x11);
                *(float2*)((float*)C + (size_t)row0 * N + col + 32)       = make_float2(y00, y01);
                *(float2*)((float*)C + (size_t)(row0 + 8) * N + col + 32) = make_float2(y10, y11);
            }
        }
    }
}

__global__ __launch_bounds__(128, 2) void fp16_gemm_qkv(const __half* __restrict__ A,
                                                        const __half* __restrict__ Bt,
                                                        const float* __restrict__ bias,
                                                        __half* __restrict__ C,
                                                        int M, int N, int K)
{
    extern __shared__ uint32_t dsm[];
    gemm_body<__half, true>(A, Bt, bias, C, M, N, K, dsm);
}
__global__ __launch_bounds__(128, 2) void fp16_gemm_f(const __half* __restrict__ A,
                                                      const __half* __restrict__ Bt,
                                                      const float* __restrict__ bias,
                                                      float* __restrict__ C,
                                                      int M, int N, int K)
{
    extern __shared__ uint32_t dsm[];
    gemm_body<float, false>(A, Bt, bias, C, M, N, K, dsm);
}

// ---------------- Flash attention, FP16, 32-key tiles (round-15 exact) ----------------
__global__ __launch_bounds__(128, 3) void attn_tc_kernel(const __half* __restrict__ qkv,
                                                         const int* __restrict__ mask,
                                                         __half* __restrict__ ctx)
{
    __shared__ __align__(16) __half Ksh[2][32][72];  // [key][dim]
    __shared__ __align__(16) __half Vth[2][64][42];  // [dim][key]
    __shared__ float Bias[2][32];

    int qb = blockIdx.x, h = blockIdx.y, b = blockIdx.z;
    int tid = threadIdx.x, w = tid >> 5, lane = tid & 31;
    int gq = lane >> 2, tq = lane & 3;

    const __half* qbase = qkv + ((size_t)(b*SS) + qb*64 + w*16) * H3 + h*HD;
    uint32_t qf[4][4];
#pragma unroll
    for (int j = 0; j < 4; j++) {
        const __half* q0 = qbase + (size_t)gq*H3     + j*16 + 2*tq;
        const __half* q1 = qbase + (size_t)(gq+8)*H3 + j*16 + 2*tq;
        __half2 a0 = *(const __half2*)(q0);
        __half2 a1 = *(const __half2*)(q1);
        __half2 a2 = *(const __half2*)(q0 + 8);
        __half2 a3 = *(const __half2*)(q1 + 8);
        qf[j][0] = packh2(__low2float(a0)*0.125f, __high2float(a0)*0.125f);
        qf[j][1] = packh2(__low2float(a1)*0.125f, __high2float(a1)*0.125f);
        qf[j][2] = packh2(__low2float(a2)*0.125f, __high2float(a2)*0.125f);
        qf[j][3] = packh2(__low2float(a3)*0.125f, __high2float(a3)*0.125f);
    }

    float o[8][4];
#pragma unroll
    for (int nt = 0; nt < 8; nt++)
#pragma unroll
        for (int e = 0; e < 4; e++) o[nt][e] = 0.f;
    float m0 = -1e30f, m1 = -1e30f, l0 = 0.f, l1 = 0.f;

    int row0 = qb*64 + w*16 + gq;
    int ntiles = 2*qb + 2;

    int lr = tid >> 4, lc = (tid & 15) << 2;

    uint2  kreg[4], vreg[4];
    float  breg = 0.f;

    const __half* kbase0 = qkv + (size_t)(b*SS) * H3 + HH + h*HD;

    {
        const __half* kb = kbase0;
        const __half* vb = kb + HH;
#pragma unroll
        for (int it = 0; it < 4; it++) {
            int r = lr + it*8;
            kreg[it] = *(const uint2*)(kb + (size_t)r*H3 + lc);
            vreg[it] = *(const uint2*)(vb + (size_t)r*H3 + lc);
        }
        if (tid < 32) breg = (1.0f - (float)mask[b*SS + tid]) * -10000.0f;
#pragma unroll
        for (int it = 0; it < 4; it++) {
            int r = lr + it*8;
            *(uint2*)&Ksh[0][r][lc] = kreg[it];
            __half2 v0 = *(__half2*)&vreg[it].x;
            __half2 v1 = *(__half2*)&vreg[it].y;
            Vth[0][lc+0][r] = __low2half(v0);
            Vth[0][lc+1][r] = __high2half(v0);
            Vth[0][lc+2][r] = __low2half(v1);
            Vth[0][lc+3][r] = __high2half(v1);
        }
        if (tid < 32) Bias[0][tid] = breg;
    }
    __syncthreads();

    for (int kt = 0; kt < ntiles; kt++) {
        int buf = kt & 1;
        bool more = (kt + 1) < ntiles;

        if (more) {
            const __half* kb = kbase0 + (size_t)((kt+1)*32) * H3;
            const __half* vb = kb + HH;
#pragma unroll
            for (int it = 0; it < 4; it++) {
                int r = lr + it*8;
                kreg[it] = *(const uint2*)(kb + (size_t)r*H3 + lc);
                vreg[it] = *(const uint2*)(vb + (size_t)r*H3 + lc);
            }
            if (tid < 32) breg = (1.0f - (float)mask[b*SS + (kt+1)*32 + tid]) * -10000.0f;
        }

        // ---- S = Q K^T ----
        float sc[4][4];
#pragma unroll
        for (int nt = 0; nt < 4; nt++)
#pragma unroll
            for (int e = 0; e < 4; e++) sc[nt][e] = 0.f;

#pragma unroll
        for (int j = 0; j < 4; j++) {
#pragma unroll
            for (int nt = 0; nt < 4; nt++) {
                uint32_t bh[2];
                bh[0] = *(const uint32_t*)&Ksh[buf][nt*8 + gq][j*16 + 2*tq];
                bh[1] = *(const uint32_t*)&Ksh[buf][nt*8 + gq][j*16 + 8 + 2*tq];
                mma_f16(sc[nt], qf[j], bh);
            }
        }

        // ---- bias + causal mask ----
#pragma unroll
        for (int nt = 0; nt < 4; nt++) {
            int k0 = kt*32 + nt*8 + 2*tq;
            float bs0 = Bias[buf][nt*8 + 2*tq], bs1 = Bias[buf][nt*8 + 2*tq + 1];
            sc[nt][0] += bs0; sc[nt][1] += bs1;
            sc[nt][2] += bs0; sc[nt][3] += bs1;
            if (k0     > row0)     sc[nt][0] = -10000.0f;
            if (k0 + 1 > row0)     sc[nt][1] = -10000.0f;
            if (k0     > row0 + 8) sc[nt][2] = -10000.0f;
            if (k0 + 1 > row0 + 8) sc[nt][3] = -10000.0f;
        }

        // ---- online softmax ----
        float tm0 = -1e30f, tm1 = -1e30f;
#pragma unroll
        for (int nt = 0; nt < 4; nt++) {
            tm0 = fmaxf(tm0, fmaxf(sc[nt][0], sc[nt][1]));
            tm1 = fmaxf(tm1, fmaxf(sc[nt][2], sc[nt][3]));
        }
        tm0 = fmaxf(tm0, __shfl_xor_sync(0xffffffffu, tm0, 1));
        tm0 = fmaxf(tm0, __shfl_xor_sync(0xffffffffu, tm0, 2));
        tm1 = fmaxf(tm1, __shfl_xor_sync(0xffffffffu, tm1, 1));
        tm1 = fmaxf(tm1, __shfl_xor_sync(0xffffffffu, tm1, 2));

        float nm0 = fmaxf(m0, tm0), nm1 = fmaxf(m1, tm1);
        float c0 = __expf(m0 - nm0), c1 = __expf(m1 - nm1);
        m0 = nm0; m1 = nm1;

        float s0 = 0.f, s1 = 0.f;
#pragma unroll
        for (int nt = 0; nt < 4; nt++) {
            sc[nt][0] = __expf(sc[nt][0] - nm0); s0 += sc[nt][0];
            sc[nt][1] = __expf(sc[nt][1] - nm0); s0 += sc[nt][1];
            sc[nt][2] = __expf(sc[nt][2] - nm1); s1 += sc[nt][2];
            sc[nt][3] = __expf(sc[nt][3] - nm1); s1 += sc[nt][3];
        }
        l0 = l0*c0 + s0;
        l1 = l1*c1 + s1;

#pragma unroll
        for (int nt = 0; nt < 8; nt++) {
            o[nt][0] *= c0; o[nt][1] *= c0;
            o[nt][2] *= c1; o[nt][3] *= c1;
        }

        // ---- O += P V ----
#pragma unroll
        for (int c = 0; c < 2; c++) {
            uint32_t a[4];
            a[0] = packh2(sc[2*c    ][0], sc[2*c    ][1]);
            a[1] = packh2(sc[2*c    ][2], sc[2*c    ][3]);
            a[2] = packh2(sc[2*c + 1][0], sc[2*c + 1][1]);
            a[3] = packh2(sc[2*c + 1][2], sc[2*c + 1][3]);
#pragma unroll
            for (int nt = 0; nt < 8; nt++) {
                uint32_t bv[2];
                bv[0] = *(const uint32_t*)&Vth[buf][nt*8 + gq][c*16 + 2*tq];
                bv[1] = *(const uint32_t*)&Vth[buf][nt*8 + gq][c*16 + 8 + 2*tq];
                mma_f16(o[nt], a, bv);
            }
        }

        if (more) {
            int nb = buf ^ 1;
#pragma unroll
            for (int it = 0; it < 4; it++) {
                int r = lr + it*8;
                *(uint2*)&Ksh[nb][r][lc] = kreg[it];
                __half2 v0 = *(__half2*)&vreg[it].x;
                __half2 v1 = *(__half2*)&vreg[it].y;
                Vth[nb][lc+0][r] = __low2half(v0);
                Vth[nb][lc+1][r] = __high2half(v0);
                Vth[nb][lc+2][r] = __low2half(v1);
                Vth[nb][lc+3][r] = __high2half(v1);
            }
            if (tid < 32) Bias[nb][tid] = breg;
        }
        __syncthreads();
    }

    // ---- epilogue ----
    l0 += __shfl_xor_sync(0xffffffffu, l0, 1);
    l0 += __shfl_xor_sync(0xffffffffu, l0, 2);
    l1 += __shfl_xor_sync(0xffffffffu, l1, 1);
    l1 += __shfl_xor_sync(0xffffffffu, l1, 2);
    float inv0 = 1.0f / l0, inv1 = 1.0f / l1;
    __half* cb = ctx + ((size_t)(b*SS) + qb*64 + w*16) * HH + h*HD;
#pragma unroll
    for (int nt = 0; nt < 8; nt++) {
        __half2 u0 = __floats2half2_rn(o[nt][0]*inv0, o[nt][1]*inv0);
        __half2 u1 = __floats2half2_rn(o[nt][2]*inv1, o[nt][3]*inv1);
        *(__half2*)(cb + (size_t)gq*HH      + nt*8 + 2*tq) = u0;
        *(__half2*)(cb + (size_t)(gq+8)*HH  + nt*8 + 2*tq) = u1;
    }
}

// ---------------- launch ----------------
extern "C" void kernel_launch(void* const* d_in, const int* in_sizes, int n_in,
                              void* d_out, int out_size)
{
    const float* x     = (const float*)d_in[0];
    const int*   maskp = (const int*)  d_in[1];
    const float* nw    = (const float*)d_in[2];
    const float* nb    = (const float*)d_in[3];
    const float* qkvw  = (const float*)d_in[4];
    const float* qkvb  = (const float*)d_in[5];
    const float* ow    = (const float*)d_in[6];
    const float* ob    = (const float*)d_in[7];
    float* out = (float*)d_out;

    __half *xn, *qkvB, *ctx, *wq, *wo;
    cudaGetSymbolAddress((void**)&xn,   g_xn);
    cudaGetSymbolAddress((void**)&qkvB, g_qkv);
    cudaGetSymbolAddress((void**)&ctx,  g_ctx);
    cudaGetSymbolAddress((void**)&wq,   g_wq);
    cudaGetSymbolAddress((void**)&wo,   g_wo);

    cudaFuncSetAttribute(fp16_gemm_qkv, cudaFuncAttributeMaxDynamicSharedMemorySize, GEMM_SMEM);
    cudaFuncSetAttribute(fp16_gemm_f,   cudaFuncAttributeMaxDynamicSharedMemorySize, GEMM_SMEM);

    ln_kernel<<<BS, 256>>>(x, nw, nb, xn);
    transpose_w<<<dim3(H3/32, HH/32), dim3(32, 8)>>>(qkvw, wq, HH, H3);
    transpose_w<<<dim3(HH/32, HH/32), dim3(32, 8)>>>(ow,   wo, HH, HH);
    fp16_gemm_qkv<<<dim3(H3/128, BS/128), 128, GEMM_SMEM>>>(xn, wq, qkvb, qkvB, BS, H3, HH);
    attn_tc_kernel<<<dim3(SS/64, NHH, BB), 128>>>(qkvB, maskp, ctx);
    fp16_gemm_f<<<dim3(HH/128, BS/128), 128, GEMM_SMEM>>>(ctx, wo, ob, out, BS, HH, HH);
}